// round 4
// baseline (speedup 1.0000x reference)
#include <cuda_runtime.h>
#include <cuda_bf16.h>

#define N_NODES 50000
#define N_EDGES 800000
#define HDIM    128
#define DEPTH   4
#define G_GRAPHS 512
#define BN_EPS  1e-5f

// ---------------- scratch (static device memory; no allocs) ----------------
// float4-typed to guarantee 16B alignment for vector ld/st
__device__ float4 g_h4  [N_NODES * 32];   // layer input  [N,128]
__device__ float4 g_hw4 [N_NODES * 32];   // h @ W        [N,128]
__device__ float4 g_agg4[N_NODES * 32];   // aggregated   [N,128]
__device__ float  g_dinv[N_NODES];
__device__ int    g_rowcnt[N_NODES];      // in-degree histogram
__device__ int    g_rowptr[N_NODES + 1];  // CSR row pointers (by dst)
__device__ int    g_cursor[N_NODES];      // fill cursors
__device__ int    g_csr_src[N_EDGES];     // CSR column (src node)
__device__ float  g_csr_w  [N_EDGES];     // dinv[src] per edge
__device__ float  g_part[250 * 2 * HDIM]; // BN partial sums
__device__ float  g_bn[2 * HDIM];         // BN scale / shift
__device__ float  g_counts[G_GRAPHS];

// ---------------- init ----------------
__global__ void k_zero(float* __restrict__ out) {
    int i = blockIdx.x * 256 + threadIdx.x;
    if (i < G_GRAPHS * HDIM) out[i] = 0.f;
    if (i < N_NODES)         g_rowcnt[i] = 0;
    if (i < G_GRAPHS)        g_counts[i] = 0.f;
}

// ---------------- degree histogram (int) ----------------
__global__ void k_deg(const int* __restrict__ ei) {
    int e = blockIdx.x * 256 + threadIdx.x;
    if (e < N_EDGES) atomicAdd(&g_rowcnt[ei[N_EDGES + e]], 1);
}

__global__ void k_dinv() {
    int i = blockIdx.x * 256 + threadIdx.x;
    if (i < N_NODES) g_dinv[i] = rsqrtf((float)g_rowcnt[i] + 1.0f);
}

// ---------------- exclusive scan of rowcnt -> rowptr (single block) --------
__global__ __launch_bounds__(1024) void k_scan() {
    __shared__ int warp_sums[32];
    __shared__ int s_base;
    const int tid = threadIdx.x, lane = tid & 31, wid = tid >> 5;
    if (tid == 0) s_base = 0;
    __syncthreads();
    for (int start = 0; start < N_NODES; start += 1024) {
        int i = start + tid;
        int v = (i < N_NODES) ? g_rowcnt[i] : 0;
        int s = v;
#pragma unroll
        for (int off = 1; off < 32; off <<= 1) {
            int t = __shfl_up_sync(0xffffffffu, s, off);
            if (lane >= off) s += t;
        }
        if (lane == 31) warp_sums[wid] = s;
        __syncthreads();
        if (wid == 0) {
            int ws = warp_sums[lane];
#pragma unroll
            for (int off = 1; off < 32; off <<= 1) {
                int t = __shfl_up_sync(0xffffffffu, ws, off);
                if (lane >= off) ws += t;
            }
            warp_sums[lane] = ws;
        }
        __syncthreads();
        int warp_off = (wid == 0) ? 0 : warp_sums[wid - 1];
        if (i < N_NODES) g_rowptr[i] = s_base + warp_off + s - v;
        __syncthreads();
        if (tid == 1023) s_base += warp_sums[31];
        __syncthreads();
    }
    if (tid == 0) g_rowptr[N_NODES] = N_EDGES;
}

__global__ void k_cursor_init() {
    int i = blockIdx.x * 256 + threadIdx.x;
    if (i < N_NODES) g_cursor[i] = g_rowptr[i];
}

// ---------------- CSR fill ----------------
__global__ void k_fill(const int* __restrict__ ei) {
    int e = blockIdx.x * 256 + threadIdx.x;
    if (e >= N_EDGES) return;
    int src = ei[e];
    int dst = ei[N_EDGES + e];
    int pos = atomicAdd(&g_cursor[dst], 1);
    g_csr_src[pos] = src;
    g_csr_w[pos]   = g_dinv[src];
}

// ---------------- GEMM: C[nrows,128] = A[nrows,128] @ W[128,128] (+bias) ---
__global__ __launch_bounds__(256) void k_gemm(const float* __restrict__ A,
                                              const float* __restrict__ W,
                                              const float* __restrict__ bias,
                                              float* __restrict__ C,
                                              int nrows) {
    __shared__ float sA[64][32];
    __shared__ float sW[32][128];
    const int tid = threadIdx.x;
    const int tx  = tid & 31;
    const int ty  = tid >> 5;
    const int m0  = blockIdx.x * 64;

    float4 acc[8];
#pragma unroll
    for (int r = 0; r < 8; r++) acc[r] = make_float4(0.f, 0.f, 0.f, 0.f);

    for (int kc = 0; kc < 128; kc += 32) {
#pragma unroll
        for (int i = 0; i < 8; i++) {
            int idx = tid + i * 256;
            int m = idx >> 5, k = idx & 31;
            int row = m0 + m;
            sA[m][k] = (row < nrows) ? A[row * 128 + kc + k] : 0.f;
        }
#pragma unroll
        for (int i = 0; i < 16; i++) {
            int idx = tid + i * 256;
            int k = idx >> 7, n = idx & 127;
            sW[k][n] = W[(kc + k) * 128 + n];
        }
        __syncthreads();
#pragma unroll
        for (int k = 0; k < 32; k++) {
            float4 w = *(const float4*)&sW[k][tx * 4];
#pragma unroll
            for (int r = 0; r < 8; r++) {
                float a = sA[ty * 8 + r][k];
                acc[r].x += a * w.x; acc[r].y += a * w.y;
                acc[r].z += a * w.z; acc[r].w += a * w.w;
            }
        }
        __syncthreads();
    }
#pragma unroll
    for (int r = 0; r < 8; r++) {
        int row = m0 + ty * 8 + r;
        if (row < nrows) {
            float4 v = acc[r];
            if (bias != nullptr) {
                v.x += bias[tx * 4 + 0]; v.y += bias[tx * 4 + 1];
                v.z += bias[tx * 4 + 2]; v.w += bias[tx * 4 + 3];
            }
            *(float4*)&C[row * 128 + tx * 4] = v;
        }
    }
}

// ---------------- pull aggregation: one warp per dst node ------------------
// agg[d] = sum_{e: dst=d} dinv[s]*dinv[d]*hw[s]  +  dinv[d]^2*hw[d]  +  bias
__global__ __launch_bounds__(256) void k_agg(const float* __restrict__ bias) {
    int node = blockIdx.x * 8 + (threadIdx.x >> 5);
    if (node >= N_NODES) return;
    int lane = threadIdx.x & 31;
    int beg = g_rowptr[node], end = g_rowptr[node + 1];
    float dv = g_dinv[node];

    float4 acc = make_float4(0.f, 0.f, 0.f, 0.f);
#pragma unroll 2
    for (int j = beg; j < end; j++) {
        int src   = __ldg(&g_csr_src[j]);
        float w   = __ldg(&g_csr_w[j]) * dv;
        float4 v  = g_hw4[src * 32 + lane];
        acc.x += w * v.x; acc.y += w * v.y;
        acc.z += w * v.z; acc.w += w * v.w;
    }
    float d2 = dv * dv;
    float4 s = g_hw4[node * 32 + lane];
    acc.x = acc.x + d2 * s.x + bias[lane * 4 + 0];
    acc.y = acc.y + d2 * s.y + bias[lane * 4 + 1];
    acc.z = acc.z + d2 * s.z + bias[lane * 4 + 2];
    acc.w = acc.w + d2 * s.w + bias[lane * 4 + 3];
    g_agg4[node * 32 + lane] = acc;
}

// ---------------- BN: partial sums (atomic-free) ---------------------------
__global__ __launch_bounds__(128) void k_bnreduce() {
    const int c = threadIdx.x;
    const int rows_per = 200;                 // 250 * 200 = 50000
    int r0 = blockIdx.x * rows_per;
    int r1 = r0 + rows_per; if (r1 > N_NODES) r1 = N_NODES;
    const float* agg = (const float*)g_agg4;
    float s = 0.f, q = 0.f;
    for (int r = r0; r < r1; r++) {
        float v = fmaxf(__ldg(&agg[r * HDIM + c]), 0.f);
        s += v; q += v * v;
    }
    g_part[blockIdx.x * 2 * HDIM + c] = s;
    g_part[blockIdx.x * 2 * HDIM + HDIM + c] = q;
}

__global__ __launch_bounds__(128) void k_bnfinal(const float* __restrict__ gamma,
                                                 const float* __restrict__ beta) {
    const int c = threadIdx.x;
    float s = 0.f, q = 0.f;
    for (int b = 0; b < 250; b++) {
        s += g_part[b * 2 * HDIM + c];
        q += g_part[b * 2 * HDIM + HDIM + c];
    }
    float inv_n = 1.0f / (float)N_NODES;
    float mu  = s * inv_n;
    float var = q * inv_n - mu * mu;
    float sc  = rsqrtf(var + BN_EPS) * gamma[c];
    g_bn[c]        = sc;
    g_bn[HDIM + c] = beta[c] - mu * sc;
}

// ---------------- BN apply: h = relu(agg)*scale + shift --------------------
__global__ void k_bnapply() {
    int idx = blockIdx.x * 256 + threadIdx.x;        // over N*32 float4s
    if (idx >= N_NODES * 32) return;
    int c4 = (idx & 31) * 4;
    float4 v = g_agg4[idx];
    float4 o;
#pragma unroll
    for (int j = 0; j < 4; j++) {
        int c = c4 + j;
        float val = fmaxf((&v.x)[j], 0.f);
        (&o.x)[j] = val * g_bn[c] + g_bn[HDIM + c];
    }
    g_h4[idx] = o;
}

// ---------------- pooling --------------------------------------------------
__global__ void k_counts(const int* __restrict__ batch) {
    int i = blockIdx.x * 256 + threadIdx.x;
    if (i < N_NODES) atomicAdd(&g_counts[batch[i]], 1.0f);
}

__global__ void k_pool(const int* __restrict__ batch, float* __restrict__ out) {
    int idx = blockIdx.x * 256 + threadIdx.x;        // over N*32 float4s
    if (idx >= N_NODES * 32) return;
    int row = idx >> 5;
    int g = batch[row];
    float4 v = g_agg4[idx];
    float* o = out + g * HDIM + (idx & 31) * 4;
    atomicAdd(o + 0, v.x);
    atomicAdd(o + 1, v.y);
    atomicAdd(o + 2, v.z);
    atomicAdd(o + 3, v.w);
}

__global__ void k_div(float* __restrict__ out) {
    int i = blockIdx.x * 256 + threadIdx.x;
    if (i < G_GRAPHS * HDIM) out[i] /= fmaxf(g_counts[i >> 7], 1.0f);
}

// ---------------- launcher -------------------------------------------------
extern "C" void kernel_launch(void* const* d_in, const int* in_sizes, int n_in,
                              void* d_out, int out_size) {
    const float* x      = (const float*)d_in[0];
    const int*   ei     = (const int*)d_in[1];     // int32 (JAX coerces int64)
    const int*   batch  = (const int*)d_in[2];     // int32
    const float* W_emb  = (const float*)d_in[3];
    const float* b_emb  = (const float*)d_in[4];
    const float* W_conv = (const float*)d_in[5];
    const float* b_conv = (const float*)d_in[6];
    const float* gamma  = (const float*)d_in[7];
    const float* beta   = (const float*)d_in[8];
    float* out = (float*)d_out;

    float *p_h, *p_hw;
    cudaGetSymbolAddress((void**)&p_h,  g_h4);
    cudaGetSymbolAddress((void**)&p_hw, g_hw4);

    const int ELEM_BLOCKS = (N_NODES * 32 + 255) / 256;   // 6250
    const int GEMM_BLOCKS = (N_NODES + 63) / 64;          // 782
    const int NODE_BLOCKS = (N_NODES + 255) / 256;        // 196
    const int EDGE_BLOCKS = (N_EDGES + 255) / 256;        // 3125
    const int AGG_BLOCKS  = (N_NODES + 7) / 8;            // 6250

    // graph preprocessing
    k_zero<<<(G_GRAPHS * HDIM + 255) / 256, 256>>>(out);
    k_deg<<<EDGE_BLOCKS, 256>>>(ei);
    k_dinv<<<NODE_BLOCKS, 256>>>();
    k_scan<<<1, 1024>>>();
    k_cursor_init<<<NODE_BLOCKS, 256>>>();
    k_fill<<<EDGE_BLOCKS, 256>>>(ei);
    k_counts<<<NODE_BLOCKS, 256>>>(batch);

    // embedding: h = x @ W_emb + b_emb
    k_gemm<<<GEMM_BLOCKS, 256>>>(x, W_emb, b_emb, p_h, N_NODES);

    for (int i = 0; i < DEPTH; i++) {
        k_gemm<<<GEMM_BLOCKS, 256>>>(p_h, W_conv + i * HDIM * HDIM, nullptr,
                                     p_hw, N_NODES);
        k_agg<<<AGG_BLOCKS, 256>>>(b_conv + i * HDIM);
        if (i < DEPTH - 1) {
            k_bnreduce<<<250, 128>>>();
            k_bnfinal<<<1, 128>>>(gamma + i * HDIM, beta + i * HDIM);
            k_bnapply<<<ELEM_BLOCKS, 256>>>();
        }
    }

    k_pool<<<ELEM_BLOCKS, 256>>>(batch, out);
    k_div<<<(G_GRAPHS * HDIM + 255) / 256, 256>>>(out);
}

// round 7
// speedup vs baseline: 1.0565x; 1.0565x over previous
#include <cuda_runtime.h>
#include <cuda_bf16.h>

#define N_NODES 50000
#define N_EDGES 800000
#define HDIM    128
#define DEPTH   4
#define G_GRAPHS 512
#define BN_EPS  1e-5f
#define SCAN_BLOCKS 196   // ceil(50000/256)

// ---------------- scratch (static device memory; no allocs) ----------------
__device__ float4 g_h4  [N_NODES * 32];   // embedding output [N,128]
__device__ float4 g_hw4 [N_NODES * 32];   // h @ W            [N,128]
__device__ float4 g_agg4[N_NODES * 32];   // aggregated       [N,128]
__device__ float  g_dinv[N_NODES];
__device__ int    g_rowcnt[N_NODES];      // in-degree histogram
__device__ int    g_rowptr[N_NODES + 1];  // CSR row pointers (by dst)
__device__ int    g_cursor[N_NODES];      // fill cursors
__device__ int    g_csr_src[N_EDGES];     // CSR column (src node)
__device__ float  g_csr_w  [N_EDGES];     // dinv[src] per edge
__device__ float  g_part[250 * 2 * HDIM]; // BN partial sums
__device__ float  g_bn[2 * HDIM];         // BN scale / shift
__device__ int    g_blocksum[SCAN_BLOCKS];
__device__ int    g_blockoff[SCAN_BLOCKS];
__device__ int    g_gstart[G_GRAPHS + 1]; // per-graph row ranges (batch sorted)

// ---------------- init ----------------
__global__ void k_zero_cnt() {
    int i = blockIdx.x * 256 + threadIdx.x;
    if (i < N_NODES) g_rowcnt[i] = 0;
}

// ---------------- degree histogram ----------------
__global__ void k_deg(const int* __restrict__ ei) {
    int e = blockIdx.x * 256 + threadIdx.x;
    if (e < N_EDGES) atomicAdd(&g_rowcnt[ei[N_EDGES + e]], 1);
}

__global__ void k_dinv() {
    int i = blockIdx.x * 256 + threadIdx.x;
    if (i < N_NODES) g_dinv[i] = rsqrtf((float)g_rowcnt[i] + 1.0f);
}

// ---------------- multi-block exclusive scan of rowcnt -> rowptr -----------
// stage 1: per-block sums
__global__ __launch_bounds__(256) void k_scan1() {
    __shared__ int wsum[8];
    int t = threadIdx.x, lane = t & 31, w = t >> 5;
    int i = blockIdx.x * 256 + t;
    int v = (i < N_NODES) ? g_rowcnt[i] : 0;
    int s = v;
#pragma unroll
    for (int off = 1; off < 32; off <<= 1) {
        int tmp = __shfl_up_sync(0xffffffffu, s, off);
        if (lane >= off) s += tmp;
    }
    if (lane == 31) wsum[w] = s;
    __syncthreads();
    if (t == 0) {
        int tot = 0;
#pragma unroll
        for (int j = 0; j < 8; j++) tot += wsum[j];
        g_blocksum[blockIdx.x] = tot;
    }
}

// stage 2: scan the 196 block sums (one small block)
__global__ __launch_bounds__(256) void k_scan2() {
    __shared__ int wsum[8];
    int t = threadIdx.x, lane = t & 31, w = t >> 5;
    int v = (t < SCAN_BLOCKS) ? g_blocksum[t] : 0;
    int s = v;
#pragma unroll
    for (int off = 1; off < 32; off <<= 1) {
        int tmp = __shfl_up_sync(0xffffffffu, s, off);
        if (lane >= off) s += tmp;
    }
    if (lane == 31) wsum[w] = s;
    __syncthreads();
    if (t == 0) {
        int run = 0;
#pragma unroll
        for (int j = 0; j < 8; j++) { int x = wsum[j]; wsum[j] = run; run += x; }
    }
    __syncthreads();
    if (t < SCAN_BLOCKS) g_blockoff[t] = wsum[w] + s - v;   // exclusive
}

// stage 3: in-block exclusive scan + global offset; write rowptr & cursor
__global__ __launch_bounds__(256) void k_scan3() {
    __shared__ int wsum[8];
    int t = threadIdx.x, lane = t & 31, w = t >> 5;
    int i = blockIdx.x * 256 + t;
    int v = (i < N_NODES) ? g_rowcnt[i] : 0;
    int s = v;
#pragma unroll
    for (int off = 1; off < 32; off <<= 1) {
        int tmp = __shfl_up_sync(0xffffffffu, s, off);
        if (lane >= off) s += tmp;
    }
    if (lane == 31) wsum[w] = s;
    __syncthreads();
    if (t == 0) {
        int run = 0;
#pragma unroll
        for (int j = 0; j < 8; j++) { int x = wsum[j]; wsum[j] = run; run += x; }
    }
    __syncthreads();
    if (i < N_NODES) {
        int excl = g_blockoff[blockIdx.x] + wsum[w] + s - v;
        g_rowptr[i] = excl;
        g_cursor[i] = excl;
    }
    if (blockIdx.x == 0 && t == 0) g_rowptr[N_NODES] = N_EDGES;
}

// ---------------- CSR fill ----------------
__global__ void k_fill(const int* __restrict__ ei) {
    int e = blockIdx.x * 256 + threadIdx.x;
    if (e >= N_EDGES) return;
    int src = ei[e];
    int dst = ei[N_EDGES + e];
    int pos = atomicAdd(&g_cursor[dst], 1);
    g_csr_src[pos] = src;
    g_csr_w[pos]   = g_dinv[src];
}

// ---------------- graph boundaries (batch is sorted) ----------------
__global__ void k_gbound(const int* __restrict__ batch) {
    int i = blockIdx.x * 256 + threadIdx.x;
    if (i >= N_NODES) return;
    int b = batch[i];
    int prev = (i == 0) ? -1 : batch[i - 1];
    for (int g = prev + 1; g <= b; g++) g_gstart[g] = i;
    if (i == N_NODES - 1)
        for (int g = b + 1; g <= G_GRAPHS; g++) g_gstart[g] = N_NODES;
}

// ---------------- GEMM: C = pre(A) @ W (+bias) -----------------------------
// If bn != null, A is pre-transformed elementwise: a <- max(a,0)*bn[k] + bn[128+k]
// (fused relu + batchnorm of the PREVIOUS layer applied on load).
__global__ __launch_bounds__(256) void k_gemm(const float* __restrict__ A,
                                              const float* __restrict__ W,
                                              const float* __restrict__ bias,
                                              const float* __restrict__ bn,
                                              float* __restrict__ C,
                                              int nrows) {
    __shared__ float sA[64][32];
    __shared__ float sW[32][128];
    const int tid = threadIdx.x;
    const int tx  = tid & 31;
    const int ty  = tid >> 5;
    const int m0  = blockIdx.x * 64;

    float4 acc[8];
#pragma unroll
    for (int r = 0; r < 8; r++) acc[r] = make_float4(0.f, 0.f, 0.f, 0.f);

    for (int kc = 0; kc < 128; kc += 32) {
#pragma unroll
        for (int i = 0; i < 8; i++) {
            int idx = tid + i * 256;
            int m = idx >> 5, k = idx & 31;
            int row = m0 + m;
            float a = (row < nrows) ? A[row * 128 + kc + k] : 0.f;
            if (bn != nullptr)
                a = fmaxf(a, 0.f) * bn[kc + k] + bn[HDIM + kc + k];
            sA[m][k] = a;
        }
#pragma unroll
        for (int i = 0; i < 16; i++) {
            int idx = tid + i * 256;
            int k = idx >> 7, n = idx & 127;
            sW[k][n] = W[(kc + k) * 128 + n];
        }
        __syncthreads();
#pragma unroll
        for (int k = 0; k < 32; k++) {
            float4 w = *(const float4*)&sW[k][tx * 4];
#pragma unroll
            for (int r = 0; r < 8; r++) {
                float a = sA[ty * 8 + r][k];
                acc[r].x += a * w.x; acc[r].y += a * w.y;
                acc[r].z += a * w.z; acc[r].w += a * w.w;
            }
        }
        __syncthreads();
    }
#pragma unroll
    for (int r = 0; r < 8; r++) {
        int row = m0 + ty * 8 + r;
        if (row < nrows) {
            float4 v = acc[r];
            if (bias != nullptr) {
                v.x += bias[tx * 4 + 0]; v.y += bias[tx * 4 + 1];
                v.z += bias[tx * 4 + 2]; v.w += bias[tx * 4 + 3];
            }
            *(float4*)&C[row * 128 + tx * 4] = v;
        }
    }
}

// ---------------- pull aggregation: one warp per dst node ------------------
__global__ __launch_bounds__(256) void k_agg(const float* __restrict__ bias) {
    int node = blockIdx.x * 8 + (threadIdx.x >> 5);
    if (node >= N_NODES) return;
    int lane = threadIdx.x & 31;
    int beg = g_rowptr[node], end = g_rowptr[node + 1];
    float dv = g_dinv[node];

    float4 acc = make_float4(0.f, 0.f, 0.f, 0.f);
#pragma unroll 2
    for (int j = beg; j < end; j++) {
        int src   = __ldg(&g_csr_src[j]);
        float w   = __ldg(&g_csr_w[j]) * dv;
        float4 v  = g_hw4[src * 32 + lane];
        acc.x += w * v.x; acc.y += w * v.y;
        acc.z += w * v.z; acc.w += w * v.w;
    }
    float d2 = dv * dv;
    float4 s = g_hw4[node * 32 + lane];
    acc.x = acc.x + d2 * s.x + bias[lane * 4 + 0];
    acc.y = acc.y + d2 * s.y + bias[lane * 4 + 1];
    acc.z = acc.z + d2 * s.z + bias[lane * 4 + 2];
    acc.w = acc.w + d2 * s.w + bias[lane * 4 + 3];
    g_agg4[node * 32 + lane] = acc;
}

// ---------------- BN: partial sums over relu(agg) (atomic-free) ------------
__global__ __launch_bounds__(128) void k_bnreduce() {
    const int c = threadIdx.x;
    const int rows_per = 200;                 // 250 * 200 = 50000
    int r0 = blockIdx.x * rows_per;
    int r1 = r0 + rows_per; if (r1 > N_NODES) r1 = N_NODES;
    const float* agg = (const float*)g_agg4;
    float s = 0.f, q = 0.f;
    for (int r = r0; r < r1; r++) {
        float v = fmaxf(__ldg(&agg[r * HDIM + c]), 0.f);
        s += v; q += v * v;
    }
    g_part[blockIdx.x * 2 * HDIM + c] = s;
    g_part[blockIdx.x * 2 * HDIM + HDIM + c] = q;
}

__global__ __launch_bounds__(128) void k_bnfinal(const float* __restrict__ gamma,
                                                 const float* __restrict__ beta) {
    const int c = threadIdx.x;
    float s = 0.f, q = 0.f;
    for (int b = 0; b < 250; b++) {
        s += g_part[b * 2 * HDIM + c];
        q += g_part[b * 2 * HDIM + HDIM + c];
    }
    float inv_n = 1.0f / (float)N_NODES;
    float mu  = s * inv_n;
    float var = q * inv_n - mu * mu;
    float sc  = rsqrtf(var + BN_EPS) * gamma[c];
    g_bn[c]        = sc;
    g_bn[HDIM + c] = beta[c] - mu * sc;
}

// ---------------- pooling: one block per graph (batch sorted, no atomics) --
__global__ __launch_bounds__(128) void k_pool(float* __restrict__ out) {
    int g = blockIdx.x, c = threadIdx.x;
    int r0 = g_gstart[g], r1 = g_gstart[g + 1];
    const float* agg = (const float*)g_agg4;
    float s = 0.f;
    for (int r = r0; r < r1; r++) s += __ldg(&agg[r * HDIM + c]);
    out[g * HDIM + c] = s / fmaxf((float)(r1 - r0), 1.0f);
}

// ---------------- launcher -------------------------------------------------
extern "C" void kernel_launch(void* const* d_in, const int* in_sizes, int n_in,
                              void* d_out, int out_size) {
    const float* x      = (const float*)d_in[0];
    const int*   ei     = (const int*)d_in[1];     // int32 (JAX coerces int64)
    const int*   batch  = (const int*)d_in[2];     // int32
    const float* W_emb  = (const float*)d_in[3];
    const float* b_emb  = (const float*)d_in[4];
    const float* W_conv = (const float*)d_in[5];
    const float* b_conv = (const float*)d_in[6];
    const float* gamma  = (const float*)d_in[7];
    const float* beta   = (const float*)d_in[8];
    float* out = (float*)d_out;

    float *p_h, *p_hw, *p_agg, *p_bn;
    cudaGetSymbolAddress((void**)&p_h,   g_h4);
    cudaGetSymbolAddress((void**)&p_hw,  g_hw4);
    cudaGetSymbolAddress((void**)&p_agg, g_agg4);
    cudaGetSymbolAddress((void**)&p_bn,  g_bn);

    const int GEMM_BLOCKS = (N_NODES + 63) / 64;          // 782
    const int NODE_BLOCKS = (N_NODES + 255) / 256;        // 196
    const int EDGE_BLOCKS = (N_EDGES + 255) / 256;        // 3125
    const int AGG_BLOCKS  = (N_NODES + 7) / 8;            // 6250

    // graph preprocessing
    k_zero_cnt<<<NODE_BLOCKS, 256>>>();
    k_deg<<<EDGE_BLOCKS, 256>>>(ei);
    k_dinv<<<NODE_BLOCKS, 256>>>();
    k_scan1<<<SCAN_BLOCKS, 256>>>();
    k_scan2<<<1, 256>>>();
    k_scan3<<<SCAN_BLOCKS, 256>>>();
    k_fill<<<EDGE_BLOCKS, 256>>>(ei);
    k_gbound<<<NODE_BLOCKS, 256>>>(batch);

    // embedding: h = x @ W_emb + b_emb
    k_gemm<<<GEMM_BLOCKS, 256>>>(x, W_emb, b_emb, nullptr, p_h, N_NODES);

    for (int i = 0; i < DEPTH; i++) {
        const float* Ain = (i == 0) ? p_h : p_agg;
        const float* bn  = (i == 0) ? nullptr : p_bn;   // fused relu+BN of prev layer
        k_gemm<<<GEMM_BLOCKS, 256>>>(Ain, W_conv + i * HDIM * HDIM, nullptr,
                                     bn, p_hw, N_NODES);
        k_agg<<<AGG_BLOCKS, 256>>>(b_conv + i * HDIM);
        if (i < DEPTH - 1) {
            k_bnreduce<<<250, 128>>>();
            k_bnfinal<<<1, 128>>>(gamma + i * HDIM, beta + i * HDIM);
        }
    }

    k_pool<<<G_GRAPHS, 128>>>(out);
}

// round 9
// speedup vs baseline: 1.2692x; 1.2014x over previous
#include <cuda_runtime.h>
#include <cuda_bf16.h>

#define N_NODES 50000
#define N_EDGES 800000
#define HDIM    128
#define DEPTH   4
#define G_GRAPHS 512
#define BN_EPS  1e-5f
#define SCAN_BLOCKS 196   // ceil(50000/256)

// ---------------- scratch (static device memory; no allocs) ----------------
__device__ float4 g_h4  [N_NODES * 32];   // embedding output [N,128]
__device__ float4 g_hw4 [N_NODES * 32];   // h @ W            [N,128]
__device__ float4 g_agg4[N_NODES * 32];   // aggregated       [N,128]
__device__ float  g_dinv[N_NODES];
__device__ int    g_rowcnt[N_NODES];      // in-degree histogram
__device__ int    g_rowptr[N_NODES + 1];  // CSR row pointers (by dst)
__device__ int    g_cursor[N_NODES];      // fill cursors
__device__ int    g_csr_src[N_EDGES];     // CSR column (src node)
__device__ float  g_csr_w  [N_EDGES];     // dinv[src] per edge
__device__ float  g_part[250 * 2 * HDIM]; // BN partial sums
__device__ float  g_bn[2 * HDIM];         // BN scale / shift
__device__ int    g_blocksum[SCAN_BLOCKS];
__device__ int    g_blockoff[SCAN_BLOCKS];
__device__ int    g_gstart[G_GRAPHS + 1]; // per-graph row ranges (batch sorted)

// ---------------- packed f32x2 helpers (Blackwell FFMA2) -------------------
__device__ __forceinline__ void fma2(unsigned long long& d,
                                     unsigned long long a,
                                     unsigned long long b) {
    asm("fma.rn.f32x2 %0, %1, %2, %0;" : "+l"(d) : "l"(a), "l"(b));
}
__device__ __forceinline__ unsigned long long pack2(float x, float y) {
    unsigned long long r;
    asm("mov.b64 %0, {%1, %2};" : "=l"(r) : "f"(x), "f"(y));
    return r;
}
__device__ __forceinline__ float lo32(unsigned long long v) {
    return __uint_as_float((unsigned int)(v & 0xffffffffull));
}
__device__ __forceinline__ float hi32(unsigned long long v) {
    return __uint_as_float((unsigned int)(v >> 32));
}

// ---------------- init ----------------
__global__ void k_zero_cnt() {
    int i = blockIdx.x * 256 + threadIdx.x;
    if (i < N_NODES) g_rowcnt[i] = 0;
}

// ---------------- degree histogram ----------------
__global__ void k_deg(const int* __restrict__ ei) {
    int e = blockIdx.x * 256 + threadIdx.x;
    if (e < N_EDGES) atomicAdd(&g_rowcnt[ei[N_EDGES + e]], 1);
}

__global__ void k_dinv() {
    int i = blockIdx.x * 256 + threadIdx.x;
    if (i < N_NODES) g_dinv[i] = rsqrtf((float)g_rowcnt[i] + 1.0f);
}

// ---------------- multi-block exclusive scan of rowcnt -> rowptr -----------
__global__ __launch_bounds__(256) void k_scan1() {
    __shared__ int wsum[8];
    int t = threadIdx.x, lane = t & 31, w = t >> 5;
    int i = blockIdx.x * 256 + t;
    int v = (i < N_NODES) ? g_rowcnt[i] : 0;
    int s = v;
#pragma unroll
    for (int off = 1; off < 32; off <<= 1) {
        int tmp = __shfl_up_sync(0xffffffffu, s, off);
        if (lane >= off) s += tmp;
    }
    if (lane == 31) wsum[w] = s;
    __syncthreads();
    if (t == 0) {
        int tot = 0;
#pragma unroll
        for (int j = 0; j < 8; j++) tot += wsum[j];
        g_blocksum[blockIdx.x] = tot;
    }
}

__global__ __launch_bounds__(256) void k_scan2() {
    __shared__ int wsum[8];
    int t = threadIdx.x, lane = t & 31, w = t >> 5;
    int v = (t < SCAN_BLOCKS) ? g_blocksum[t] : 0;
    int s = v;
#pragma unroll
    for (int off = 1; off < 32; off <<= 1) {
        int tmp = __shfl_up_sync(0xffffffffu, s, off);
        if (lane >= off) s += tmp;
    }
    if (lane == 31) wsum[w] = s;
    __syncthreads();
    if (t == 0) {
        int run = 0;
#pragma unroll
        for (int j = 0; j < 8; j++) { int x = wsum[j]; wsum[j] = run; run += x; }
    }
    __syncthreads();
    if (t < SCAN_BLOCKS) g_blockoff[t] = wsum[w] + s - v;   // exclusive
}

__global__ __launch_bounds__(256) void k_scan3() {
    __shared__ int wsum[8];
    int t = threadIdx.x, lane = t & 31, w = t >> 5;
    int i = blockIdx.x * 256 + t;
    int v = (i < N_NODES) ? g_rowcnt[i] : 0;
    int s = v;
#pragma unroll
    for (int off = 1; off < 32; off <<= 1) {
        int tmp = __shfl_up_sync(0xffffffffu, s, off);
        if (lane >= off) s += tmp;
    }
    if (lane == 31) wsum[w] = s;
    __syncthreads();
    if (t == 0) {
        int run = 0;
#pragma unroll
        for (int j = 0; j < 8; j++) { int x = wsum[j]; wsum[j] = run; run += x; }
    }
    __syncthreads();
    if (i < N_NODES) {
        int excl = g_blockoff[blockIdx.x] + wsum[w] + s - v;
        g_rowptr[i] = excl;
        g_cursor[i] = excl;
    }
    if (blockIdx.x == 0 && t == 0) g_rowptr[N_NODES] = N_EDGES;
}

// ---------------- CSR fill ----------------
__global__ void k_fill(const int* __restrict__ ei) {
    int e = blockIdx.x * 256 + threadIdx.x;
    if (e >= N_EDGES) return;
    int src = ei[e];
    int dst = ei[N_EDGES + e];
    int pos = atomicAdd(&g_cursor[dst], 1);
    g_csr_src[pos] = src;
    g_csr_w[pos]   = g_dinv[src];
}

// ---------------- graph boundaries (batch is sorted) ----------------
__global__ void k_gbound(const int* __restrict__ batch) {
    int i = blockIdx.x * 256 + threadIdx.x;
    if (i >= N_NODES) return;
    int b = batch[i];
    int prev = (i == 0) ? -1 : batch[i - 1];
    for (int g = prev + 1; g <= b; g++) g_gstart[g] = i;
    if (i == N_NODES - 1)
        for (int g = b + 1; g <= G_GRAPHS; g++) g_gstart[g] = N_NODES;
}

// ---------------- GEMM (FFMA2): C = pre(A) @ W (+bias) ---------------------
// A staged TRANSPOSED (sAT[k][m], pad 66 keeps LDS.64 8B-aligned & banks clean)
// so M-row-pairs arrive pre-packed for fma.rn.f32x2.
// If bn != null: a <- max(a,0)*bn[k] + bn[128+k] fused on load.
__global__ __launch_bounds__(256) void k_gemm(const float* __restrict__ A,
                                              const float* __restrict__ W,
                                              const float* __restrict__ bias,
                                              const float* __restrict__ bn,
                                              float* __restrict__ C,
                                              int nrows) {
    __shared__ float sAT[32][66];
    __shared__ float sW[32][128];
    const int tid = threadIdx.x;
    const int tx  = tid & 31;    // -> cols tx*4 .. tx*4+3
    const int ty  = tid >> 5;    // -> rows ty*8 .. ty*8+7
    const int m0  = blockIdx.x * 64;

    unsigned long long acc[4][4];   // [row-pair][col] ; pair = rows {2p,2p+1}
#pragma unroll
    for (int p = 0; p < 4; p++)
#pragma unroll
        for (int c = 0; c < 4; c++) acc[p][c] = 0ull;

    for (int kc = 0; kc < 128; kc += 32) {
        // stage A transposed: consecutive tid -> consecutive k (coalesced LDG)
#pragma unroll
        for (int i = 0; i < 8; i++) {
            int idx = tid + i * 256;
            int m = idx >> 5, k = idx & 31;
            int row = m0 + m;
            float a = (row < nrows) ? A[row * 128 + kc + k] : 0.f;
            if (bn != nullptr)
                a = fmaxf(a, 0.f) * bn[kc + k] + bn[HDIM + kc + k];
            sAT[k][m] = a;
        }
#pragma unroll
        for (int i = 0; i < 16; i++) {
            int idx = tid + i * 256;
            int k = idx >> 7, n = idx & 127;
            sW[k][n] = W[(kc + k) * 128 + n];
        }
        __syncthreads();
#pragma unroll
        for (int k = 0; k < 32; k++) {
            // 4 row-pairs via LDS.64 (warp-broadcast: all lanes share ty)
            float2 a01 = *(const float2*)&sAT[k][ty * 8 + 0];
            float2 a23 = *(const float2*)&sAT[k][ty * 8 + 2];
            float2 a45 = *(const float2*)&sAT[k][ty * 8 + 4];
            float2 a67 = *(const float2*)&sAT[k][ty * 8 + 6];
            unsigned long long ap[4] = {
                pack2(a01.x, a01.y), pack2(a23.x, a23.y),
                pack2(a45.x, a45.y), pack2(a67.x, a67.y)
            };
            float4 w = *(const float4*)&sW[k][tx * 4];
            unsigned long long wp[4] = {
                pack2(w.x, w.x), pack2(w.y, w.y),
                pack2(w.z, w.z), pack2(w.w, w.w)
            };
#pragma unroll
            for (int p = 0; p < 4; p++)
#pragma unroll
                for (int c = 0; c < 4; c++)
                    fma2(acc[p][c], ap[p], wp[c]);
        }
        __syncthreads();
    }
    // epilogue: unpack pairs, add bias, store float4 per row
#pragma unroll
    for (int r = 0; r < 8; r++) {
        int row = m0 + ty * 8 + r;
        if (row < nrows) {
            int p = r >> 1;
            float4 v;
            if (r & 1) {
                v.x = hi32(acc[p][0]); v.y = hi32(acc[p][1]);
                v.z = hi32(acc[p][2]); v.w = hi32(acc[p][3]);
            } else {
                v.x = lo32(acc[p][0]); v.y = lo32(acc[p][1]);
                v.z = lo32(acc[p][2]); v.w = lo32(acc[p][3]);
            }
            if (bias != nullptr) {
                v.x += bias[tx * 4 + 0]; v.y += bias[tx * 4 + 1];
                v.z += bias[tx * 4 + 2]; v.w += bias[tx * 4 + 3];
            }
            *(float4*)&C[row * 128 + tx * 4] = v;
        }
    }
}

// ---------------- pull aggregation: one warp per dst node ------------------
__global__ __launch_bounds__(256) void k_agg(const float* __restrict__ bias) {
    int node = blockIdx.x * 8 + (threadIdx.x >> 5);
    if (node >= N_NODES) return;
    int lane = threadIdx.x & 31;
    int beg = g_rowptr[node], end = g_rowptr[node + 1];
    float dv = g_dinv[node];

    float4 acc = make_float4(0.f, 0.f, 0.f, 0.f);
#pragma unroll 2
    for (int j = beg; j < end; j++) {
        int src   = __ldg(&g_csr_src[j]);
        float w   = __ldg(&g_csr_w[j]) * dv;
        float4 v  = g_hw4[src * 32 + lane];
        acc.x += w * v.x; acc.y += w * v.y;
        acc.z += w * v.z; acc.w += w * v.w;
    }
    float d2 = dv * dv;
    float4 s = g_hw4[node * 32 + lane];
    acc.x = acc.x + d2 * s.x + bias[lane * 4 + 0];
    acc.y = acc.y + d2 * s.y + bias[lane * 4 + 1];
    acc.z = acc.z + d2 * s.z + bias[lane * 4 + 2];
    acc.w = acc.w + d2 * s.w + bias[lane * 4 + 3];
    g_agg4[node * 32 + lane] = acc;
}

// ---------------- BN: partial sums over relu(agg) (atomic-free) ------------
__global__ __launch_bounds__(128) void k_bnreduce() {
    const int c = threadIdx.x;
    const int rows_per = 200;                 // 250 * 200 = 50000
    int r0 = blockIdx.x * rows_per;
    int r1 = r0 + rows_per; if (r1 > N_NODES) r1 = N_NODES;
    const float* agg = (const float*)g_agg4;
    float s = 0.f, q = 0.f;
    for (int r = r0; r < r1; r++) {
        float v = fmaxf(__ldg(&agg[r * HDIM + c]), 0.f);
        s += v; q += v * v;
    }
    g_part[blockIdx.x * 2 * HDIM + c] = s;
    g_part[blockIdx.x * 2 * HDIM + HDIM + c] = q;
}

__global__ __launch_bounds__(128) void k_bnfinal(const float* __restrict__ gamma,
                                                 const float* __restrict__ beta) {
    const int c = threadIdx.x;
    float s = 0.f, q = 0.f;
    for (int b = 0; b < 250; b++) {
        s += g_part[b * 2 * HDIM + c];
        q += g_part[b * 2 * HDIM + HDIM + c];
    }
    float inv_n = 1.0f / (float)N_NODES;
    float mu  = s * inv_n;
    float var = q * inv_n - mu * mu;
    float sc  = rsqrtf(var + BN_EPS) * gamma[c];
    g_bn[c]        = sc;
    g_bn[HDIM + c] = beta[c] - mu * sc;
}

// ---------------- pooling: one block per graph (batch sorted, no atomics) --
__global__ __launch_bounds__(128) void k_pool(float* __restrict__ out) {
    int g = blockIdx.x, c = threadIdx.x;
    int r0 = g_gstart[g], r1 = g_gstart[g + 1];
    const float* agg = (const float*)g_agg4;
    float s = 0.f;
    for (int r = r0; r < r1; r++) s += __ldg(&agg[r * HDIM + c]);
    out[g * HDIM + c] = s / fmaxf((float)(r1 - r0), 1.0f);
}

// ---------------- launcher -------------------------------------------------
extern "C" void kernel_launch(void* const* d_in, const int* in_sizes, int n_in,
                              void* d_out, int out_size) {
    const float* x      = (const float*)d_in[0];
    const int*   ei     = (const int*)d_in[1];     // int32 (JAX coerces int64)
    const int*   batch  = (const int*)d_in[2];     // int32
    const float* W_emb  = (const float*)d_in[3];
    const float* b_emb  = (const float*)d_in[4];
    const float* W_conv = (const float*)d_in[5];
    const float* b_conv = (const float*)d_in[6];
    const float* gamma  = (const float*)d_in[7];
    const float* beta   = (const float*)d_in[8];
    float* out = (float*)d_out;

    float *p_h, *p_hw, *p_agg, *p_bn;
    cudaGetSymbolAddress((void**)&p_h,   g_h4);
    cudaGetSymbolAddress((void**)&p_hw,  g_hw4);
    cudaGetSymbolAddress((void**)&p_agg, g_agg4);
    cudaGetSymbolAddress((void**)&p_bn,  g_bn);

    const int GEMM_BLOCKS = (N_NODES + 63) / 64;          // 782
    const int NODE_BLOCKS = (N_NODES + 255) / 256;        // 196
    const int EDGE_BLOCKS = (N_EDGES + 255) / 256;        // 3125
    const int AGG_BLOCKS  = (N_NODES + 7) / 8;            // 6250

    // graph preprocessing
    k_zero_cnt<<<NODE_BLOCKS, 256>>>();
    k_deg<<<EDGE_BLOCKS, 256>>>(ei);
    k_dinv<<<NODE_BLOCKS, 256>>>();
    k_scan1<<<SCAN_BLOCKS, 256>>>();
    k_scan2<<<1, 256>>>();
    k_scan3<<<SCAN_BLOCKS, 256>>>();
    k_fill<<<EDGE_BLOCKS, 256>>>(ei);
    k_gbound<<<NODE_BLOCKS, 256>>>(batch);

    // embedding: h = x @ W_emb + b_emb
    k_gemm<<<GEMM_BLOCKS, 256>>>(x, W_emb, b_emb, nullptr, p_h, N_NODES);

    for (int i = 0; i < DEPTH; i++) {
        const float* Ain = (i == 0) ? p_h : p_agg;
        const float* bn  = (i == 0) ? nullptr : p_bn;   // fused relu+BN of prev layer
        k_gemm<<<GEMM_BLOCKS, 256>>>(Ain, W_conv + i * HDIM * HDIM, nullptr,
                                     bn, p_hw, N_NODES);
        k_agg<<<AGG_BLOCKS, 256>>>(b_conv + i * HDIM);
        if (i < DEPTH - 1) {
            k_bnreduce<<<250, 128>>>();
            k_bnfinal<<<1, 128>>>(gamma + i * HDIM, beta + i * HDIM);
        }
    }

    k_pool<<<G_GRAPHS, 128>>>(out);
}